// round 4
// baseline (speedup 1.0000x reference)
#include <cuda_runtime.h>
#include <cuda_fp16.h>
#include <cstdint>

#define IN_F   4096
#define OUT_F  4096
#define M_ROWS 8192

// fp16 scratch: merged effective weight and converted activations.
__device__ __half g_Wh[(size_t)OUT_F * IN_F];
__device__ __half g_Xh[(size_t)M_ROWS * IN_F];

__constant__ float NF4[16] = {
    -1.0f, -0.6961928009986877f, -0.5250730514526367f, -0.39491748809814453f,
    -0.28444138169288635f, -0.18477343022823334f, -0.09105003625154495f, 0.0f,
    0.07958029955625534f, 0.16093020141124725f, 0.24611230194568634f,
    0.33791524171829224f, 0.4407098889350891f, 0.5626170039176941f,
    0.7229568362236023f, 1.0f
};

__device__ __forceinline__ uint32_t smem_u32(const void* p) {
    uint32_t a;
    asm("{ .reg .u64 t; cvta.to.shared.u64 t, %1; cvt.u32.u64 %0, t; }" : "=r"(a) : "l"(p));
    return a;
}

// ---------------------------------------------------------------------------
// Kernel A: convert x (fp32) -> g_Xh (fp16). 8 elems/thread.
// ---------------------------------------------------------------------------
__global__ void convert_x_kernel(const float* __restrict__ x) {
    size_t i = ((size_t)blockIdx.x * 256 + threadIdx.x) * 8;
    float4 v0 = *(const float4*)(x + i);
    float4 v1 = *(const float4*)(x + i + 4);
    __half2 h0 = __floats2half2_rn(v0.x, v0.y);
    __half2 h1 = __floats2half2_rn(v0.z, v0.w);
    __half2 h2 = __floats2half2_rn(v1.x, v1.y);
    __half2 h3 = __floats2half2_rn(v1.z, v1.w);
    uint4 o;
    o.x = *(uint32_t*)&h0; o.y = *(uint32_t*)&h1;
    o.z = *(uint32_t*)&h2; o.w = *(uint32_t*)&h3;
    *(uint4*)&g_Xh[i] = o;
}

// ---------------------------------------------------------------------------
// Kernel B: W_eff = NF4 dequant * absmax + lora_B @ lora_A  (fp16 out)
// ---------------------------------------------------------------------------
__global__ void build_weff_kernel(const int* __restrict__ qweight,
                                  const float* __restrict__ absmax,
                                  const float* __restrict__ lA,
                                  const float* __restrict__ lB) {
    __shared__ float Bsh[64][64];
    __shared__ float Ash[64][128];

    const int tid = threadIdx.x;
    const int o0 = blockIdx.y * 64;
    const int i0 = blockIdx.x * 128;

    for (int t = tid; t < 64 * 64; t += 256) {
        int o = t >> 6, r = t & 63;
        Bsh[r][o] = lB[(o0 + o) * 64 + r];
    }
    for (int t = tid; t < 64 * 128; t += 256) {
        int r = t >> 7, c = t & 127;
        Ash[r][c] = lA[r * IN_F + i0 + c];
    }
    __syncthreads();

    const int oo0 = (tid >> 4) * 4;
    const int ii0 = (tid & 15) * 8;

    float acc[4][8];
#pragma unroll
    for (int a = 0; a < 4; a++)
#pragma unroll
        for (int b = 0; b < 8; b++) acc[a][b] = 0.0f;

#pragma unroll 4
    for (int r = 0; r < 64; r++) {
        float4 a0 = *(const float4*)&Ash[r][ii0];
        float4 a1 = *(const float4*)&Ash[r][ii0 + 4];
#pragma unroll
        for (int oo = 0; oo < 4; oo++) {
            float bv = Bsh[r][oo0 + oo];
            acc[oo][0] += bv * a0.x; acc[oo][1] += bv * a0.y;
            acc[oo][2] += bv * a0.z; acc[oo][3] += bv * a0.w;
            acc[oo][4] += bv * a1.x; acc[oo][5] += bv * a1.y;
            acc[oo][6] += bv * a1.z; acc[oo][7] += bv * a1.w;
        }
    }

#pragma unroll
    for (int oo = 0; oo < 4; oo++) {
        const int o = o0 + oo0 + oo;
        const size_t k = (size_t)o * IN_F + i0 + ii0;
        const int4 qv = ((const int4*)qweight)[k >> 3];
        const float am = absmax[k >> 6];

        float w[8];
        w[0] = NF4[qv.x & 15];  w[1] = NF4[(qv.x >> 4) & 15];
        w[2] = NF4[qv.y & 15];  w[3] = NF4[(qv.y >> 4) & 15];
        w[4] = NF4[qv.z & 15];  w[5] = NF4[(qv.z >> 4) & 15];
        w[6] = NF4[qv.w & 15];  w[7] = NF4[(qv.w >> 4) & 15];

        __half2 h0 = __floats2half2_rn(w[0] * am + acc[oo][0], w[1] * am + acc[oo][1]);
        __half2 h1 = __floats2half2_rn(w[2] * am + acc[oo][2], w[3] * am + acc[oo][3]);
        __half2 h2 = __floats2half2_rn(w[4] * am + acc[oo][4], w[5] * am + acc[oo][5]);
        __half2 h3 = __floats2half2_rn(w[6] * am + acc[oo][6], w[7] * am + acc[oo][7]);
        uint4 pk;
        pk.x = *(uint32_t*)&h0; pk.y = *(uint32_t*)&h1;
        pk.z = *(uint32_t*)&h2; pk.w = *(uint32_t*)&h3;
        *(uint4*)&g_Wh[k] = pk;
    }
}

// ---------------------------------------------------------------------------
// Kernel C: persistent fp16 mma.sync GEMM  out[8192,4096] = g_Xh @ g_Wh^T
// BM=128, BN=256, BK=64 (128B swizzled rows), 3-stage cp.async, 256 threads.
// Warp grid 2(m) x 4(n); warp tile 64x64; mma m16n8k16, fp32 accum.
// ---------------------------------------------------------------------------
constexpr int BM = 128, BN = 256, BK = 64, S = 3;
constexpr int NT = IN_F / BK;                   // 64 k-tiles
constexpr int A_BYTES = BM * 128;               // 16384
constexpr int B_BYTES = BN * 128;               // 32768
constexpr int STAGE = A_BYTES + B_BYTES;        // 49152
constexpr int SMEM_TOTAL = 1024 + S * STAGE;    // 148480
constexpr int TOTAL_TILES = (M_ROWS / BM) * (OUT_F / BN);  // 1024

__device__ __forceinline__ void mma_f16(float c[4], const uint32_t a[4],
                                        uint32_t b0, uint32_t b1) {
    asm volatile(
        "mma.sync.aligned.m16n8k16.row.col.f32.f16.f16.f32 "
        "{%0,%1,%2,%3}, {%4,%5,%6,%7}, {%8,%9}, {%0,%1,%2,%3};"
        : "+f"(c[0]), "+f"(c[1]), "+f"(c[2]), "+f"(c[3])
        : "r"(a[0]), "r"(a[1]), "r"(a[2]), "r"(a[3]), "r"(b0), "r"(b1));
}

__device__ __forceinline__ void ldsm4(uint32_t& r0, uint32_t& r1,
                                      uint32_t& r2, uint32_t& r3, uint32_t addr) {
    asm volatile("ldmatrix.sync.aligned.m8n8.x4.shared.b16 {%0,%1,%2,%3}, [%4];"
                 : "=r"(r0), "=r"(r1), "=r"(r2), "=r"(r3) : "r"(addr));
}

// cp.async one stage: A 1024 + B 2048 16B-chunks, 256 threads.
__device__ __forceinline__ void issue_stage(uint32_t sA, uint32_t sB,
                                            const __half* xb, const __half* wb,
                                            int tid) {
#pragma unroll
    for (int r = 0; r < 4; r++) {
        int i = tid + r * 256;
        int row = i >> 3, c = i & 7;
        uint32_t off = (uint32_t)(row * 128 + ((c * 16) ^ ((row & 7) << 4)));
        const __half* src = xb + (size_t)row * IN_F + c * 8;
        asm volatile("cp.async.cg.shared.global [%0], [%1], 16;\n"
                     :: "r"(sA + off), "l"(src));
    }
#pragma unroll
    for (int r = 0; r < 8; r++) {
        int i = tid + r * 256;
        int row = i >> 3, c = i & 7;
        uint32_t off = (uint32_t)(row * 128 + ((c * 16) ^ ((row & 7) << 4)));
        const __half* src = wb + (size_t)row * IN_F + c * 8;
        asm volatile("cp.async.cg.shared.global [%0], [%1], 16;\n"
                     :: "r"(sB + off), "l"(src));
    }
}

__global__ void __launch_bounds__(256, 1)
gemm_f16_kernel(float* __restrict__ out) {
    extern __shared__ char sm[];
    const uint32_t stage0 = (smem_u32(sm) + 1023) & ~1023u;

    const int tid = threadIdx.x;
    const int wid = tid >> 5;
    const int lane = tid & 31;
    const int warp_m = wid & 1;        // 0..1 -> 64 rows
    const int warp_n = wid >> 1;       // 0..3 -> 64 cols
    const int g = lane >> 3;           // ldmatrix tile group 0..3
    const int r = lane & 7;

    // A (mf=0..3): row = warp_m*64 + mf*16 + (g&1)*8 + r ; kconst = (g>>1)*16
    uint32_t a_rowoff[4], a_xr[4];
    const uint32_t a_kc = (uint32_t)((g >> 1) * 16);
#pragma unroll
    for (int mf = 0; mf < 4; mf++) {
        int row = warp_m * 64 + mf * 16 + (g & 1) * 8 + r;
        a_rowoff[mf] = row * 128;
        a_xr[mf] = (row & 7) << 4;
    }
    // B (pair p=0..3): row = warp_n*64 + p*16 + (g>>1)*8 + r ; kconst = (g&1)*16
    uint32_t b_rowoff[4], b_xr[4];
    const uint32_t b_kc = (uint32_t)((g & 1) * 16);
#pragma unroll
    for (int p = 0; p < 4; p++) {
        int row = warp_n * 64 + p * 16 + (g >> 1) * 8 + r;
        b_rowoff[p] = row * 128;
        b_xr[p] = (row & 7) << 4;
    }

    for (int t = blockIdx.x; t < TOTAL_TILES; t += gridDim.x) {
        const int mBase = (t >> 4) * BM;
        const int nBase = (t & 15) * BN;
        const __half* xt = g_Xh + (size_t)mBase * IN_F;
        const __half* wt = g_Wh + (size_t)nBase * IN_F;

        float acc[4][8][4];
#pragma unroll
        for (int i = 0; i < 4; i++)
#pragma unroll
            for (int j = 0; j < 8; j++)
#pragma unroll
                for (int l = 0; l < 4; l++) acc[i][j][l] = 0.0f;

        // prologue: stages 0..S-2
#pragma unroll
        for (int p = 0; p < S - 1; p++) {
            uint32_t sA = stage0 + p * STAGE;
            issue_stage(sA, sA + A_BYTES, xt + p * BK, wt + p * BK, tid);
            asm volatile("cp.async.commit_group;\n" ::: "memory");
        }

        for (int kt = 0; kt < NT; kt++) {
            asm volatile("cp.async.wait_group %0;\n" :: "n"(S - 2) : "memory");
            __syncthreads();

            // issue stage kt+S-1 (slot safe: its compute finished last iter)
            if (kt + S - 1 < NT) {
                const int s2 = (kt + S - 1) % S;
                uint32_t sA = stage0 + s2 * STAGE;
                issue_stage(sA, sA + A_BYTES,
                            xt + (kt + S - 1) * BK, wt + (kt + S - 1) * BK, tid);
            }
            asm volatile("cp.async.commit_group;\n" ::: "memory");

            const uint32_t sA = stage0 + (kt % S) * STAGE;
            const uint32_t sB = sA + A_BYTES;

#pragma unroll
            for (int q = 0; q < 4; q++) {
                uint32_t a[4][4];
#pragma unroll
                for (int mf = 0; mf < 4; mf++)
                    ldsm4(a[mf][0], a[mf][1], a[mf][2], a[mf][3],
                          sA + a_rowoff[mf] + (((q * 32) + a_kc) ^ a_xr[mf]));
                uint32_t b[8][2];
#pragma unroll
                for (int p = 0; p < 4; p++)
                    ldsm4(b[2 * p][0], b[2 * p][1], b[2 * p + 1][0], b[2 * p + 1][1],
                          sB + b_rowoff[p] + (((q * 32) + b_kc) ^ b_xr[p]));
#pragma unroll
                for (int mf = 0; mf < 4; mf++)
#pragma unroll
                    for (int nf = 0; nf < 8; nf++)
                        mma_f16(acc[mf][nf], a[mf], b[nf][0], b[nf][1]);
            }
        }
        asm volatile("cp.async.wait_group 0;\n" ::: "memory");

        // epilogue: direct STG from accumulators
#pragma unroll
        for (int mf = 0; mf < 4; mf++) {
#pragma unroll
            for (int nf = 0; nf < 8; nf++) {
                const int row = mBase + warp_m * 64 + mf * 16 + (lane >> 2);
                const int col = nBase + warp_n * 64 + nf * 8 + (lane & 3) * 2;
                *(float2*)&out[(size_t)row * OUT_F + col] =
                    make_float2(acc[mf][nf][0], acc[mf][nf][1]);
                *(float2*)&out[(size_t)(row + 8) * OUT_F + col] =
                    make_float2(acc[mf][nf][2], acc[mf][nf][3]);
            }
        }
        __syncthreads();   // all warps done with smem before next tile prologue
    }
}

// ---------------------------------------------------------------------------
extern "C" void kernel_launch(void* const* d_in, const int* in_sizes, int n_in,
                              void* d_out, int out_size) {
    const float* x  = (const float*)d_in[0];
    const int*   qw = (const int*)d_in[1];
    const float* am = (const float*)d_in[2];
    const float* lA = (const float*)d_in[3];
    const float* lB = (const float*)d_in[4];
    float*       out = (float*)d_out;

    (void)in_sizes; (void)n_in; (void)out_size;

    cudaFuncSetAttribute(gemm_f16_kernel,
                         cudaFuncAttributeMaxDynamicSharedMemorySize, SMEM_TOTAL);

    convert_x_kernel<<<(M_ROWS * IN_F / 8) / 256, 256>>>(x);
    build_weff_kernel<<<dim3(IN_F / 128, OUT_F / 64), 256>>>(qw, am, lA, lB);
    gemm_f16_kernel<<<148, 256, SMEM_TOTAL>>>(out);
}

// round 5
// speedup vs baseline: 1.0504x; 1.0504x over previous
#include <cuda_runtime.h>
#include <cuda_fp16.h>
#include <cstdint>

#define IN_F   4096
#define OUT_F  4096
#define M_ROWS 8192

// fp16 scratch: merged effective weight and converted activations.
__device__ __half g_Wh[(size_t)OUT_F * IN_F];
__device__ __half g_Xh[(size_t)M_ROWS * IN_F];

__constant__ float NF4[16] = {
    -1.0f, -0.6961928009986877f, -0.5250730514526367f, -0.39491748809814453f,
    -0.28444138169288635f, -0.18477343022823334f, -0.09105003625154495f, 0.0f,
    0.07958029955625534f, 0.16093020141124725f, 0.24611230194568634f,
    0.33791524171829224f, 0.4407098889350891f, 0.5626170039176941f,
    0.7229568362236023f, 1.0f
};

__device__ __forceinline__ uint32_t smem_u32(const void* p) {
    uint32_t a;
    asm("{ .reg .u64 t; cvta.to.shared.u64 t, %1; cvt.u32.u64 %0, t; }" : "=r"(a) : "l"(p));
    return a;
}

// ---------------------------------------------------------------------------
// Kernel A: convert x (fp32) -> g_Xh (fp16). 8 elems/thread.
// ---------------------------------------------------------------------------
__global__ void convert_x_kernel(const float* __restrict__ x) {
    size_t i = ((size_t)blockIdx.x * 256 + threadIdx.x) * 8;
    float4 v0 = *(const float4*)(x + i);
    float4 v1 = *(const float4*)(x + i + 4);
    __half2 h0 = __floats2half2_rn(v0.x, v0.y);
    __half2 h1 = __floats2half2_rn(v0.z, v0.w);
    __half2 h2 = __floats2half2_rn(v1.x, v1.y);
    __half2 h3 = __floats2half2_rn(v1.z, v1.w);
    uint4 o;
    o.x = *(uint32_t*)&h0; o.y = *(uint32_t*)&h1;
    o.z = *(uint32_t*)&h2; o.w = *(uint32_t*)&h3;
    *(uint4*)&g_Xh[i] = o;
}

// ---------------------------------------------------------------------------
// Kernel B: W_eff = NF4 dequant * absmax + lora_B @ lora_A  (fp16 out)
// ---------------------------------------------------------------------------
__global__ void build_weff_kernel(const int* __restrict__ qweight,
                                  const float* __restrict__ absmax,
                                  const float* __restrict__ lA,
                                  const float* __restrict__ lB) {
    __shared__ float Bsh[64][64];
    __shared__ float Ash[64][128];

    const int tid = threadIdx.x;
    const int o0 = blockIdx.y * 64;
    const int i0 = blockIdx.x * 128;

    for (int t = tid; t < 64 * 64; t += 256) {
        int o = t >> 6, r = t & 63;
        Bsh[r][o] = lB[(o0 + o) * 64 + r];
    }
    for (int t = tid; t < 64 * 128; t += 256) {
        int r = t >> 7, c = t & 127;
        Ash[r][c] = lA[r * IN_F + i0 + c];
    }
    __syncthreads();

    const int oo0 = (tid >> 4) * 4;
    const int ii0 = (tid & 15) * 8;

    float acc[4][8];
#pragma unroll
    for (int a = 0; a < 4; a++)
#pragma unroll
        for (int b = 0; b < 8; b++) acc[a][b] = 0.0f;

#pragma unroll 4
    for (int r = 0; r < 64; r++) {
        float4 a0 = *(const float4*)&Ash[r][ii0];
        float4 a1 = *(const float4*)&Ash[r][ii0 + 4];
#pragma unroll
        for (int oo = 0; oo < 4; oo++) {
            float bv = Bsh[r][oo0 + oo];
            acc[oo][0] += bv * a0.x; acc[oo][1] += bv * a0.y;
            acc[oo][2] += bv * a0.z; acc[oo][3] += bv * a0.w;
            acc[oo][4] += bv * a1.x; acc[oo][5] += bv * a1.y;
            acc[oo][6] += bv * a1.z; acc[oo][7] += bv * a1.w;
        }
    }

#pragma unroll
    for (int oo = 0; oo < 4; oo++) {
        const int o = o0 + oo0 + oo;
        const size_t k = (size_t)o * IN_F + i0 + ii0;
        const int4 qv = ((const int4*)qweight)[k >> 3];
        const float am = absmax[k >> 6];

        float w[8];
        w[0] = NF4[qv.x & 15];  w[1] = NF4[(qv.x >> 4) & 15];
        w[2] = NF4[qv.y & 15];  w[3] = NF4[(qv.y >> 4) & 15];
        w[4] = NF4[qv.z & 15];  w[5] = NF4[(qv.z >> 4) & 15];
        w[6] = NF4[qv.w & 15];  w[7] = NF4[(qv.w >> 4) & 15];

        __half2 h0 = __floats2half2_rn(w[0] * am + acc[oo][0], w[1] * am + acc[oo][1]);
        __half2 h1 = __floats2half2_rn(w[2] * am + acc[oo][2], w[3] * am + acc[oo][3]);
        __half2 h2 = __floats2half2_rn(w[4] * am + acc[oo][4], w[5] * am + acc[oo][5]);
        __half2 h3 = __floats2half2_rn(w[6] * am + acc[oo][6], w[7] * am + acc[oo][7]);
        uint4 pk;
        pk.x = *(uint32_t*)&h0; pk.y = *(uint32_t*)&h1;
        pk.z = *(uint32_t*)&h2; pk.w = *(uint32_t*)&h3;
        *(uint4*)&g_Wh[k] = pk;
    }
}

// ---------------------------------------------------------------------------
// Kernel C: persistent fp16 mma.sync GEMM  out[8192,4096] = g_Xh @ g_Wh^T
// BM=128, BN=256, BK=64 (128B swizzled rows), 4-stage cp.async, 512 threads.
// Warp grid 4(m) x 4(n); warp tile 32x64; mma m16n8k16, fp32 accum.
// Output stores are evict-first (st.cs) to protect X/W L2 residency.
// ---------------------------------------------------------------------------
constexpr int BM = 128, BN = 256, BK = 64, S = 4;
constexpr int NT = IN_F / BK;                   // 64 k-tiles
constexpr int A_BYTES = BM * 128;               // 16384
constexpr int B_BYTES = BN * 128;               // 32768
constexpr int STAGE = A_BYTES + B_BYTES;        // 49152
constexpr int SMEM_TOTAL = 1024 + S * STAGE;    // 197632
constexpr int TOTAL_TILES = (M_ROWS / BM) * (OUT_F / BN);  // 1024

__device__ __forceinline__ void mma_f16(float c[4], const uint32_t a[4],
                                        uint32_t b0, uint32_t b1) {
    asm volatile(
        "mma.sync.aligned.m16n8k16.row.col.f32.f16.f16.f32 "
        "{%0,%1,%2,%3}, {%4,%5,%6,%7}, {%8,%9}, {%0,%1,%2,%3};"
        : "+f"(c[0]), "+f"(c[1]), "+f"(c[2]), "+f"(c[3])
        : "r"(a[0]), "r"(a[1]), "r"(a[2]), "r"(a[3]), "r"(b0), "r"(b1));
}

__device__ __forceinline__ void ldsm4(uint32_t& r0, uint32_t& r1,
                                      uint32_t& r2, uint32_t& r3, uint32_t addr) {
    asm volatile("ldmatrix.sync.aligned.m8n8.x4.shared.b16 {%0,%1,%2,%3}, [%4];"
                 : "=r"(r0), "=r"(r1), "=r"(r2), "=r"(r3) : "r"(addr));
}

__device__ __forceinline__ void st_cs_f2(float* p, float a, float b) {
    asm volatile("st.global.cs.v2.f32 [%0], {%1,%2};" :: "l"(p), "f"(a), "f"(b)
                 : "memory");
}

// cp.async one stage: A 1024 + B 2048 16B-chunks, 512 threads.
// .L2::256B prefetch pulls the neighboring 128B = next k-tile's data per row.
__device__ __forceinline__ void issue_stage(uint32_t sA, uint32_t sB,
                                            const __half* xb, const __half* wb,
                                            int tid) {
#pragma unroll
    for (int r = 0; r < 2; r++) {
        int i = tid + r * 512;
        int row = i >> 3, c = i & 7;
        uint32_t off = (uint32_t)(row * 128 + ((c * 16) ^ ((row & 7) << 4)));
        const __half* src = xb + (size_t)row * IN_F + c * 8;
        asm volatile("cp.async.cg.shared.global.L2::256B [%0], [%1], 16;\n"
                     :: "r"(sA + off), "l"(src));
    }
#pragma unroll
    for (int r = 0; r < 4; r++) {
        int i = tid + r * 512;
        int row = i >> 3, c = i & 7;
        uint32_t off = (uint32_t)(row * 128 + ((c * 16) ^ ((row & 7) << 4)));
        const __half* src = wb + (size_t)row * IN_F + c * 8;
        asm volatile("cp.async.cg.shared.global.L2::256B [%0], [%1], 16;\n"
                     :: "r"(sB + off), "l"(src));
    }
}

__global__ void __launch_bounds__(512, 1)
gemm_f16_kernel(float* __restrict__ out) {
    extern __shared__ char sm[];
    const uint32_t stage0 = (smem_u32(sm) + 1023) & ~1023u;

    const int tid = threadIdx.x;
    const int wid = tid >> 5;
    const int lane = tid & 31;
    const int warp_m = wid & 3;        // 0..3 -> 32 rows
    const int warp_n = wid >> 2;       // 0..3 -> 64 cols
    const int g = lane >> 3;           // ldmatrix tile group 0..3
    const int r = lane & 7;

    // A (mf=0,1): row = warp_m*32 + mf*16 + (g&1)*8 + r ; kconst = (g>>1)*16
    uint32_t a_rowoff[2], a_xr[2];
    const uint32_t a_kc = (uint32_t)((g >> 1) * 16);
#pragma unroll
    for (int mf = 0; mf < 2; mf++) {
        int row = warp_m * 32 + mf * 16 + (g & 1) * 8 + r;
        a_rowoff[mf] = row * 128;
        a_xr[mf] = (row & 7) << 4;
    }
    // B (pair p=0..3): row = warp_n*64 + p*16 + (g>>1)*8 + r ; kconst = (g&1)*16
    uint32_t b_rowoff[4], b_xr[4];
    const uint32_t b_kc = (uint32_t)((g & 1) * 16);
#pragma unroll
    for (int p = 0; p < 4; p++) {
        int row = warp_n * 64 + p * 16 + (g >> 1) * 8 + r;
        b_rowoff[p] = row * 128;
        b_xr[p] = (row & 7) << 4;
    }

    for (int t = blockIdx.x; t < TOTAL_TILES; t += gridDim.x) {
        const int mBase = (t >> 4) * BM;
        const int nBase = (t & 15) * BN;
        const __half* xt = g_Xh + (size_t)mBase * IN_F;
        const __half* wt = g_Wh + (size_t)nBase * IN_F;

        float acc[2][8][4];
#pragma unroll
        for (int i = 0; i < 2; i++)
#pragma unroll
            for (int j = 0; j < 8; j++)
#pragma unroll
                for (int l = 0; l < 4; l++) acc[i][j][l] = 0.0f;

        // prologue: stages 0..S-2
#pragma unroll
        for (int p = 0; p < S - 1; p++) {
            uint32_t sA = stage0 + p * STAGE;
            issue_stage(sA, sA + A_BYTES, xt + p * BK, wt + p * BK, tid);
            asm volatile("cp.async.commit_group;\n" ::: "memory");
        }

        for (int kt = 0; kt < NT; kt++) {
            asm volatile("cp.async.wait_group %0;\n" :: "n"(S - 2) : "memory");
            __syncthreads();

            // issue stage kt+S-1 (slot safe: its compute finished last iter)
            if (kt + S - 1 < NT) {
                const int s2 = (kt + S - 1) % S;
                uint32_t sA = stage0 + s2 * STAGE;
                issue_stage(sA, sA + A_BYTES,
                            xt + (kt + S - 1) * BK, wt + (kt + S - 1) * BK, tid);
            }
            asm volatile("cp.async.commit_group;\n" ::: "memory");

            const uint32_t sA = stage0 + (kt % S) * STAGE;
            const uint32_t sB = sA + A_BYTES;

#pragma unroll
            for (int q = 0; q < 4; q++) {
                uint32_t a[2][4];
#pragma unroll
                for (int mf = 0; mf < 2; mf++)
                    ldsm4(a[mf][0], a[mf][1], a[mf][2], a[mf][3],
                          sA + a_rowoff[mf] + (((q * 32) + a_kc) ^ a_xr[mf]));
                uint32_t b[8][2];
#pragma unroll
                for (int p = 0; p < 4; p++)
                    ldsm4(b[2 * p][0], b[2 * p][1], b[2 * p + 1][0], b[2 * p + 1][1],
                          sB + b_rowoff[p] + (((q * 32) + b_kc) ^ b_xr[p]));
#pragma unroll
                for (int mf = 0; mf < 2; mf++)
#pragma unroll
                    for (int nf = 0; nf < 8; nf++)
                        mma_f16(acc[mf][nf], a[mf], b[nf][0], b[nf][1]);
            }
        }
        asm volatile("cp.async.wait_group 0;\n" ::: "memory");

        // epilogue: direct evict-first STG from accumulators
#pragma unroll
        for (int mf = 0; mf < 2; mf++) {
#pragma unroll
            for (int nf = 0; nf < 8; nf++) {
                const int row = mBase + warp_m * 32 + mf * 16 + (lane >> 2);
                const int col = nBase + warp_n * 64 + nf * 8 + (lane & 3) * 2;
                st_cs_f2(&out[(size_t)row * OUT_F + col],
                         acc[mf][nf][0], acc[mf][nf][1]);
                st_cs_f2(&out[(size_t)(row + 8) * OUT_F + col],
                         acc[mf][nf][2], acc[mf][nf][3]);
            }
        }
        __syncthreads();   // all warps done with smem before next tile prologue
    }
}

// ---------------------------------------------------------------------------
extern "C" void kernel_launch(void* const* d_in, const int* in_sizes, int n_in,
                              void* d_out, int out_size) {
    const float* x  = (const float*)d_in[0];
    const int*   qw = (const int*)d_in[1];
    const float* am = (const float*)d_in[2];
    const float* lA = (const float*)d_in[3];
    const float* lB = (const float*)d_in[4];
    float*       out = (float*)d_out;

    (void)in_sizes; (void)n_in; (void)out_size;

    cudaFuncSetAttribute(gemm_f16_kernel,
                         cudaFuncAttributeMaxDynamicSharedMemorySize, SMEM_TOTAL);

    convert_x_kernel<<<(M_ROWS * IN_F / 8) / 256, 256>>>(x);
    build_weff_kernel<<<dim3(IN_F / 128, OUT_F / 64), 256>>>(qw, am, lA, lB);
    gemm_f16_kernel<<<148, 512, SMEM_TOTAL>>>(out);
}